// round 9
// baseline (speedup 1.0000x reference)
#include <cuda_runtime.h>
#include <cuda_bf16.h>

// RNN: out[n,t,:] = tanh(x[n,t,:]@Wx + b + h_{t-1}@Wh), h_{-1}=h0.
// N=64, T=512, D=256, H=256, all fp32.
//
// Kernel 1: xW = x@Wx + b -> g_xw (SIMT f32x2 GEMM).
// Kernel 2: recurrence, 64 clusters x 2 CTAs, 512 threads. CTA r owns output
//   columns [r*128,+128). Column j is served by a LANE PAIR (lanes 2c,2c+1),
//   each covering 64 k's; pair-combined with one shfl.xor. Warps 0-7 (A) dot
//   the LOCAL k-half -> p_s. Warps 8-15 (B) wait for the peer h half, dot it,
//   combine + tanh (even lanes), and send the new 512B half via one
//   cp.async.bulk with mbarrier::complete_tx (R8's proven exchange).

#define ULL unsigned long long

static __device__ __forceinline__ ULL pk2(float lo, float hi) {
    ULL r; asm("mov.b64 %0, {%1,%2};" : "=l"(r) : "f"(lo), "f"(hi)); return r;
}
static __device__ __forceinline__ void upk2(ULL v, float& lo, float& hi) {
    asm("mov.b64 {%0,%1}, %2;" : "=f"(lo), "=f"(hi) : "l"(v));
}
static __device__ __forceinline__ ULL f2fma(ULL a, ULL b, ULL c) {
    ULL d; asm("fma.rn.f32x2 %0, %1, %2, %3;" : "=l"(d) : "l"(a), "l"(b), "l"(c)); return d;
}
static __device__ __forceinline__ ULL f2add(ULL a, ULL b) {
    ULL d; asm("add.rn.f32x2 %0, %1, %2;" : "=l"(d) : "l"(a), "l"(b)); return d;
}
static __device__ __forceinline__ unsigned int smem_u32(const void* p) {
    unsigned int a;
    asm("{ .reg .u64 t; cvta.to.shared.u64 t, %1; cvt.u32.u64 %0, t; }"
        : "=r"(a) : "l"(p));
    return a;
}
static __device__ __forceinline__ float fast_tanh(float x) {
    float e = __expf(x + x);
    return 1.0f - __fdividef(2.0f, e + 1.0f);
}
static __device__ __forceinline__ void wait_parity(unsigned int bar, unsigned int par) {
    unsigned int done;
    asm volatile(
        "{ .reg .pred p; "
        "mbarrier.try_wait.parity.acquire.cta.shared::cta.b64 p, [%1], %2; "
        "selp.b32 %0, 1, 0, p; }"
        : "=r"(done) : "r"(bar), "r"(par) : "memory");
    while (!done) {
        asm volatile(
            "{ .reg .pred p; "
            "mbarrier.try_wait.parity.acquire.cta.shared::cta.b64 p, [%1], %2, 0x989680; "
            "selp.b32 %0, 1, 0, p; }"
            : "=r"(done) : "r"(bar), "r"(par) : "memory");
    }
}
// 64-element partial dot: 16x LDS.128, 32 FFMA2 over 4 chains (depth 8).
static __device__ __forceinline__ float dot64(const ulonglong2* hp, const ULL* W2) {
    ULL a0 = 0ULL, a1 = 0ULL, a2 = 0ULL, a3 = 0ULL;
#pragma unroll
    for (int q = 0; q < 16; q += 2) {
        ulonglong2 v0 = hp[q];
        ulonglong2 v1 = hp[q + 1];
        a0 = f2fma(v0.x, W2[2 * q],     a0);
        a1 = f2fma(v0.y, W2[2 * q + 1], a1);
        a2 = f2fma(v1.x, W2[2 * q + 2], a2);
        a3 = f2fma(v1.y, W2[2 * q + 3], a3);
    }
    ULL ss = f2add(f2add(a0, a1), f2add(a2, a3));
    float lo, hi;
    upk2(ss, lo, hi);
    return lo + hi;
}

// Scratch for the input projection (no cudaMalloc allowed).
__device__ float g_xw[64 * 512 * 256];

// ---------------------------------------------------------------------------
// Kernel 1: xW GEMM.  C[M=32768, H=256] = X[M,256] * Wx[256,256] + b
// ---------------------------------------------------------------------------
__global__ void __launch_bounds__(256) gemm_xw(const float* __restrict__ X,
                                               const float* __restrict__ Wx,
                                               const float* __restrict__ bias) {
    __shared__ __align__(16) float As[16][128];  // [k][m]
    __shared__ __align__(16) float Bs[16][128];  // [k][h]

    const int t    = threadIdx.x;
    const int m0   = blockIdx.x * 128;
    const int h0   = blockIdx.y * 128;
    const int warp = t >> 5;
    const int lane = t & 31;

    ULL acc[8][4];
#pragma unroll
    for (int p = 0; p < 8; p++)
#pragma unroll
        for (int c = 0; c < 4; c++) acc[p][c] = 0ULL;

    for (int k0 = 0; k0 < 256; k0 += 16) {
#pragma unroll
        for (int i = 0; i < 2; i++) {
            int s   = t * 2 + i;
            int row = s >> 2;
            int kq  = s & 3;
            float4 v = *(const float4*)&X[(size_t)(m0 + row) * 256 + k0 + kq * 4];
            As[kq * 4 + 0][row] = v.x;
            As[kq * 4 + 1][row] = v.y;
            As[kq * 4 + 2][row] = v.z;
            As[kq * 4 + 3][row] = v.w;
        }
#pragma unroll
        for (int i = 0; i < 2; i++) {
            int s  = t * 2 + i;
            int kr = s >> 5;
            int hq = s & 31;
            float4 v = *(const float4*)&Wx[(size_t)(k0 + kr) * 256 + h0 + hq * 4];
            *(float4*)&Bs[kr][hq * 4] = v;
        }
        __syncthreads();

#pragma unroll
        for (int kk = 0; kk < 16; kk++) {
            const ulonglong2* ar = (const ulonglong2*)&As[kk][warp * 16];
            ulonglong2 q0 = ar[0], q1 = ar[1], q2 = ar[2], q3 = ar[3];
            ULL ap[8] = {q0.x, q0.y, q1.x, q1.y, q2.x, q2.y, q3.x, q3.y};
            float4 bv = *(const float4*)&Bs[kk][lane * 4];
            ULL bs0 = pk2(bv.x, bv.x), bs1 = pk2(bv.y, bv.y);
            ULL bs2 = pk2(bv.z, bv.z), bs3 = pk2(bv.w, bv.w);
#pragma unroll
            for (int p = 0; p < 8; p++) {
                acc[p][0] = f2fma(ap[p], bs0, acc[p][0]);
                acc[p][1] = f2fma(ap[p], bs1, acc[p][1]);
                acc[p][2] = f2fma(ap[p], bs2, acc[p][2]);
                acc[p][3] = f2fma(ap[p], bs3, acc[p][3]);
            }
        }
        __syncthreads();
    }

    float4 bb = *(const float4*)&bias[h0 + lane * 4];
#pragma unroll
    for (int p = 0; p < 8; p++) {
        float lo0, hi0, lo1, hi1, lo2, hi2, lo3, hi3;
        upk2(acc[p][0], lo0, hi0);
        upk2(acc[p][1], lo1, hi1);
        upk2(acc[p][2], lo2, hi2);
        upk2(acc[p][3], lo3, hi3);
        int m = m0 + warp * 16 + p * 2;
        float4 r0 = make_float4(lo0 + bb.x, lo1 + bb.y, lo2 + bb.z, lo3 + bb.w);
        float4 r1 = make_float4(hi0 + bb.x, hi1 + bb.y, hi2 + bb.z, hi3 + bb.w);
        *(float4*)&g_xw[(size_t)m * 256 + h0 + lane * 4]       = r0;
        *(float4*)&g_xw[(size_t)(m + 1) * 256 + h0 + lane * 4] = r1;
    }
}

// ---------------------------------------------------------------------------
// Kernel 2: recurrence. grid = 128 blocks x 512 thr, cluster (2,1,1).
// ---------------------------------------------------------------------------
__global__ void __launch_bounds__(512, 1) __cluster_dims__(2, 1, 1)
rnn_scan(const float* __restrict__ h0g, const float* __restrict__ Wh,
         float* __restrict__ out) {
    __shared__ __align__(16) float hloc[2][128];   // our columns of h
    __shared__ __align__(16) float hrem[2][128];   // peer's columns (bulk-filled)
    __shared__ float p_s[2][128];                  // group A partials
    __shared__ __align__(8) ULL mbar;

    const int t     = threadIdx.x;
    const int n     = blockIdx.x >> 1;
    const int r     = blockIdx.x & 1;
    const int jbase = r * 128;
    const int grp   = t >> 8;              // 0 = A (local-half), 1 = B (remote)
    const int u     = t & 255;
    const int j     = u >> 1;              // column within local 128
    const int half  = u & 1;               // k-half of the 128-k slice
    // A dots k in [jbase,+128) (locally produced); B dots [jbase^128,+128).
    const int kbase = ((grp == 0) ? jbase : (jbase ^ 128)) + half * 64;

    // Register-resident weights: Wh[kbase+k][jbase+j], k in [0,64), k-pairs.
    ULL W2[32];
#pragma unroll
    for (int k2 = 0; k2 < 32; k2++) {
        float w0 = Wh[(size_t)(kbase + 2 * k2) * 256 + jbase + j];
        float w1 = Wh[(size_t)(kbase + 2 * k2 + 1) * 256 + jbase + j];
        W2[k2] = pk2(w0, w1);
    }

    if (t < 128)      hloc[0][t] = h0g[(size_t)n * 256 + jbase + t];
    else if (t < 256) hrem[0][t - 128] = h0g[(size_t)n * 256 + (jbase ^ 128) + (t - 128)];

    const unsigned int bar_local = smem_u32(&mbar);
    if (t == 0) {
        asm volatile("mbarrier.init.shared.b64 [%0], %1;"
                     :: "r"(bar_local), "r"(1) : "memory");
    }
    // Cluster-wide barrier: init writes visible everywhere before traffic.
    asm volatile("barrier.cluster.arrive.aligned;" ::: "memory");
    asm volatile("barrier.cluster.wait.aligned;" ::: "memory");

    const unsigned int peer = r ^ 1;
    unsigned int rem_dst[2], rem_bar;
    {
        unsigned int l0 = smem_u32(&hrem[0][0]);
        unsigned int l1 = smem_u32(&hrem[1][0]);
        asm("mapa.shared::cluster.u32 %0, %1, %2;" : "=r"(rem_dst[0]) : "r"(l0), "r"(peer));
        asm("mapa.shared::cluster.u32 %0, %1, %2;" : "=r"(rem_dst[1]) : "r"(l1), "r"(peer));
        asm("mapa.shared::cluster.u32 %0, %1, %2;" : "=r"(rem_bar) : "r"(bar_local), "r"(peer));
    }
    const unsigned int src_loc[2] = { smem_u32(&hloc[0][0]), smem_u32(&hloc[1][0]) };

    const float* xwp = g_xw + (size_t)n * 512 * 256 + jbase;

    if (grp == 0) {
        // ----- Group A: local-half dotter, never waits on the mbarrier -----
        for (int s = 0; s < 512; s++) {
            const int cur = s & 1;
            if (s > 0) {
                // Wait for B's hloc[cur] writes from step s-1.
                asm volatile("bar.sync 3, 512;" ::: "memory");
            }
            float part = dot64((const ulonglong2*)&hloc[cur][half * 64], W2);
            part += __shfl_xor_sync(0xffffffffu, part, 1);
            if (half == 0) p_s[cur][j] = part;
            asm volatile("bar.arrive 2, 512;" ::: "memory");
        }
    } else {
        // ----- Group B: remote-half dotter + combiner + sender -----
        float xw_cur = xwp[j];
        for (int s = 0; s < 512; s++) {
            const int cur = s & 1;
            const int nxt = cur ^ 1;

            // Prefetch next step's input projection.
            int sn = (s + 1 < 512) ? (s + 1) : s;
            float xw_nxt = xwp[(size_t)sn * 256 + j];

            // A's p_s[cur] ready (A arrived long ago in steady state); read it
            // into a register BEFORE the arrival wait (off the critical path).
            asm volatile("bar.sync 2, 512;" ::: "memory");
            float psv = p_s[cur][j];

            // Wait for the peer's half of h[cur] (step s-1's send).
            if (s > 0) wait_parity(bar_local, (unsigned)((s & 1) ^ 1));

            float part = dot64((const ulonglong2*)&hrem[cur][half * 64], W2);
            part += __shfl_xor_sync(0xffffffffu, part, 1);

            float hn = 0.f;
            if (half == 0) {
                float pre = xw_cur + part + psv;
                hn = fast_tanh(pre);
                hloc[nxt][j] = hn;
            }
            xw_cur = xw_nxt;

            if (s < 511) {
                // Release A for step s+1 (non-blocking).
                asm volatile("bar.arrive 3, 512;" ::: "memory");
                // B-internal: all 128 hloc[nxt] slots written (bulk src ready).
                asm volatile("bar.sync 1, 256;" ::: "memory");
                if (t == 256) {
                    asm volatile("mbarrier.arrive.expect_tx.shared::cta.b64 _, [%0], %1;"
                                 :: "r"(bar_local), "r"(512) : "memory");
                    asm volatile("fence.proxy.async.shared::cta;" ::: "memory");
                    asm volatile(
                        "cp.async.bulk.shared::cluster.shared::cta.mbarrier::complete_tx::bytes "
                        "[%0], [%1], %2, [%3];"
                        :: "r"(rem_dst[nxt]), "r"(src_loc[nxt]), "r"(512), "r"(rem_bar)
                        : "memory");
                }
            }
            if (half == 0)
                out[((size_t)n * 512 + s) * 256 + jbase + j] = hn;
        }
    }

    // Don't exit while the peer may still write into our SMEM.
    asm volatile("barrier.cluster.arrive.aligned;" ::: "memory");
    asm volatile("barrier.cluster.wait.aligned;" ::: "memory");
}

// ---------------------------------------------------------------------------
extern "C" void kernel_launch(void* const* d_in, const int* in_sizes, int n_in,
                              void* d_out, int out_size) {
    const float* x  = (const float*)d_in[0];  // (64,512,256)
    const float* h0 = (const float*)d_in[1];  // (64,256)
    const float* Wx = (const float*)d_in[2];  // (256,256)
    const float* Wh = (const float*)d_in[3];  // (256,256)
    const float* b  = (const float*)d_in[4];  // (256,)
    float* out = (float*)d_out;               // (64,512,256)

    dim3 g1(256, 2);
    gemm_xw<<<g1, 256>>>(x, Wx, b);
    rnn_scan<<<128, 512>>>(h0, Wh, out);
    (void)in_sizes; (void)n_in; (void)out_size;
}

// round 10
// speedup vs baseline: 1.4994x; 1.4994x over previous
#include <cuda_runtime.h>
#include <cuda_bf16.h>

// RNN: out[n,t,:] = tanh(x[n,t,:]@Wx + b + h_{t-1}@Wh), h_{-1}=h0.
// N=64, T=512, D=256, H=256, all fp32.
//
// Kernel 1: xW = x@Wx + b -> g_xw (SIMT f32x2 GEMM).
// Kernel 2: recurrence, 64 clusters x 2 CTAs, 256 threads (R8 structure).
//   Warps 0-3 (A) dot the LOCAL k-half -> p_s (never touch the mbarrier).
//   Warps 4-7 (B) read p_s BEFORE the arrival wait, then wait for the peer
//   half, dot it, combine + tanh, write the local half, and send it as FOUR
//   per-warp 128B cp.async.bulk chunks (syncwarp + fence + elect), removing
//   the 256-thread pre-send barrier from the critical path.

#define ULL unsigned long long

static __device__ __forceinline__ ULL pk2(float lo, float hi) {
    ULL r; asm("mov.b64 %0, {%1,%2};" : "=l"(r) : "f"(lo), "f"(hi)); return r;
}
static __device__ __forceinline__ void upk2(ULL v, float& lo, float& hi) {
    asm("mov.b64 {%0,%1}, %2;" : "=f"(lo), "=f"(hi) : "l"(v));
}
static __device__ __forceinline__ ULL f2fma(ULL a, ULL b, ULL c) {
    ULL d; asm("fma.rn.f32x2 %0, %1, %2, %3;" : "=l"(d) : "l"(a), "l"(b), "l"(c)); return d;
}
static __device__ __forceinline__ ULL f2add(ULL a, ULL b) {
    ULL d; asm("add.rn.f32x2 %0, %1, %2;" : "=l"(d) : "l"(a), "l"(b)); return d;
}
static __device__ __forceinline__ unsigned int smem_u32(const void* p) {
    unsigned int a;
    asm("{ .reg .u64 t; cvta.to.shared.u64 t, %1; cvt.u32.u64 %0, t; }"
        : "=r"(a) : "l"(p));
    return a;
}
static __device__ __forceinline__ float fast_tanh(float x) {
    float e = __expf(x + x);
    return 1.0f - __fdividef(2.0f, e + 1.0f);
}
static __device__ __forceinline__ void wait_parity(unsigned int bar, unsigned int par) {
    unsigned int done;
    asm volatile(
        "{ .reg .pred p; "
        "mbarrier.try_wait.parity.acquire.cta.shared::cta.b64 p, [%1], %2; "
        "selp.b32 %0, 1, 0, p; }"
        : "=r"(done) : "r"(bar), "r"(par) : "memory");
    while (!done) {
        asm volatile(
            "{ .reg .pred p; "
            "mbarrier.try_wait.parity.acquire.cta.shared::cta.b64 p, [%1], %2, 0x989680; "
            "selp.b32 %0, 1, 0, p; }"
            : "=r"(done) : "r"(bar), "r"(par) : "memory");
    }
}
// 128-element dot: 32x LDS.128, 64 FFMA2 over 8 accumulator chains.
static __device__ __forceinline__ float dot128(const ulonglong2* hp, const ULL* W2) {
    ULL a0 = 0ULL, a1 = 0ULL, a2 = 0ULL, a3 = 0ULL;
    ULL a4 = 0ULL, a5 = 0ULL, a6 = 0ULL, a7 = 0ULL;
#pragma unroll
    for (int q = 0; q < 32; q += 4) {
        ulonglong2 v0 = hp[q],     v1 = hp[q + 1];
        ulonglong2 v2 = hp[q + 2], v3 = hp[q + 3];
        a0 = f2fma(v0.x, W2[2 * q],     a0);
        a1 = f2fma(v0.y, W2[2 * q + 1], a1);
        a2 = f2fma(v1.x, W2[2 * q + 2], a2);
        a3 = f2fma(v1.y, W2[2 * q + 3], a3);
        a4 = f2fma(v2.x, W2[2 * q + 4], a4);
        a5 = f2fma(v2.y, W2[2 * q + 5], a5);
        a6 = f2fma(v3.x, W2[2 * q + 6], a6);
        a7 = f2fma(v3.y, W2[2 * q + 7], a7);
    }
    ULL ss = f2add(f2add(f2add(a0, a1), f2add(a2, a3)),
                   f2add(f2add(a4, a5), f2add(a6, a7)));
    float lo, hi;
    upk2(ss, lo, hi);
    return lo + hi;
}

// Scratch for the input projection (no cudaMalloc allowed).
__device__ float g_xw[64 * 512 * 256];

// ---------------------------------------------------------------------------
// Kernel 1: xW GEMM.  C[M=32768, H=256] = X[M,256] * Wx[256,256] + b
// ---------------------------------------------------------------------------
__global__ void __launch_bounds__(256) gemm_xw(const float* __restrict__ X,
                                               const float* __restrict__ Wx,
                                               const float* __restrict__ bias) {
    __shared__ __align__(16) float As[16][128];  // [k][m]
    __shared__ __align__(16) float Bs[16][128];  // [k][h]

    const int t    = threadIdx.x;
    const int m0   = blockIdx.x * 128;
    const int h0   = blockIdx.y * 128;
    const int warp = t >> 5;
    const int lane = t & 31;

    ULL acc[8][4];
#pragma unroll
    for (int p = 0; p < 8; p++)
#pragma unroll
        for (int c = 0; c < 4; c++) acc[p][c] = 0ULL;

    for (int k0 = 0; k0 < 256; k0 += 16) {
#pragma unroll
        for (int i = 0; i < 2; i++) {
            int s   = t * 2 + i;
            int row = s >> 2;
            int kq  = s & 3;
            float4 v = *(const float4*)&X[(size_t)(m0 + row) * 256 + k0 + kq * 4];
            As[kq * 4 + 0][row] = v.x;
            As[kq * 4 + 1][row] = v.y;
            As[kq * 4 + 2][row] = v.z;
            As[kq * 4 + 3][row] = v.w;
        }
#pragma unroll
        for (int i = 0; i < 2; i++) {
            int s  = t * 2 + i;
            int kr = s >> 5;
            int hq = s & 31;
            float4 v = *(const float4*)&Wx[(size_t)(k0 + kr) * 256 + h0 + hq * 4];
            *(float4*)&Bs[kr][hq * 4] = v;
        }
        __syncthreads();

#pragma unroll
        for (int kk = 0; kk < 16; kk++) {
            const ulonglong2* ar = (const ulonglong2*)&As[kk][warp * 16];
            ulonglong2 q0 = ar[0], q1 = ar[1], q2 = ar[2], q3 = ar[3];
            ULL ap[8] = {q0.x, q0.y, q1.x, q1.y, q2.x, q2.y, q3.x, q3.y};
            float4 bv = *(const float4*)&Bs[kk][lane * 4];
            ULL bs0 = pk2(bv.x, bv.x), bs1 = pk2(bv.y, bv.y);
            ULL bs2 = pk2(bv.z, bv.z), bs3 = pk2(bv.w, bv.w);
#pragma unroll
            for (int p = 0; p < 8; p++) {
                acc[p][0] = f2fma(ap[p], bs0, acc[p][0]);
                acc[p][1] = f2fma(ap[p], bs1, acc[p][1]);
                acc[p][2] = f2fma(ap[p], bs2, acc[p][2]);
                acc[p][3] = f2fma(ap[p], bs3, acc[p][3]);
            }
        }
        __syncthreads();
    }

    float4 bb = *(const float4*)&bias[h0 + lane * 4];
#pragma unroll
    for (int p = 0; p < 8; p++) {
        float lo0, hi0, lo1, hi1, lo2, hi2, lo3, hi3;
        upk2(acc[p][0], lo0, hi0);
        upk2(acc[p][1], lo1, hi1);
        upk2(acc[p][2], lo2, hi2);
        upk2(acc[p][3], lo3, hi3);
        int m = m0 + warp * 16 + p * 2;
        float4 r0 = make_float4(lo0 + bb.x, lo1 + bb.y, lo2 + bb.z, lo3 + bb.w);
        float4 r1 = make_float4(hi0 + bb.x, hi1 + bb.y, hi2 + bb.z, hi3 + bb.w);
        *(float4*)&g_xw[(size_t)m * 256 + h0 + lane * 4]       = r0;
        *(float4*)&g_xw[(size_t)(m + 1) * 256 + h0 + lane * 4] = r1;
    }
}

// ---------------------------------------------------------------------------
// Kernel 2: recurrence. grid = 128 blocks x 256 thr, cluster (2,1,1).
// ---------------------------------------------------------------------------
__global__ void __launch_bounds__(256, 1) __cluster_dims__(2, 1, 1)
rnn_scan(const float* __restrict__ h0g, const float* __restrict__ Wh,
         float* __restrict__ out) {
    __shared__ __align__(16) float hloc[2][128];   // our columns of h
    __shared__ __align__(16) float hrem[2][128];   // peer's columns (bulk-filled)
    __shared__ float p_s[2][128];                  // group A partials
    __shared__ __align__(8) ULL mbar;

    const int t     = threadIdx.x;
    const int n     = blockIdx.x >> 1;
    const int r     = blockIdx.x & 1;
    const int jbase = r * 128;
    const int j     = t & 127;
    const int g     = t >> 7;              // 0 = group A (local), 1 = group B
    const int kbase = (g == 0) ? jbase : (jbase ^ 128);

    // Register-resident weight slice: Wh[kbase+k][jbase+j], k-pairs.
    ULL W2[64];
#pragma unroll
    for (int k2 = 0; k2 < 64; k2++) {
        float w0 = Wh[(size_t)(kbase + 2 * k2) * 256 + jbase + j];
        float w1 = Wh[(size_t)(kbase + 2 * k2 + 1) * 256 + jbase + j];
        W2[k2] = pk2(w0, w1);
    }

    if (g == 0) hloc[0][j] = h0g[(size_t)n * 256 + jbase + j];
    else        hrem[0][j] = h0g[(size_t)n * 256 + (jbase ^ 128) + j];

    const unsigned int bar_local = smem_u32(&mbar);
    if (t == 0) {
        asm volatile("mbarrier.init.shared.b64 [%0], %1;"
                     :: "r"(bar_local), "r"(1) : "memory");
    }
    // Cluster-wide barrier: init writes visible everywhere before traffic.
    asm volatile("barrier.cluster.arrive.aligned;" ::: "memory");
    asm volatile("barrier.cluster.wait.aligned;" ::: "memory");

    const unsigned int peer = r ^ 1;
    unsigned int rem_dst[2], rem_bar;
    {
        unsigned int l0 = smem_u32(&hrem[0][0]);
        unsigned int l1 = smem_u32(&hrem[1][0]);
        asm("mapa.shared::cluster.u32 %0, %1, %2;" : "=r"(rem_dst[0]) : "r"(l0), "r"(peer));
        asm("mapa.shared::cluster.u32 %0, %1, %2;" : "=r"(rem_dst[1]) : "r"(l1), "r"(peer));
        asm("mapa.shared::cluster.u32 %0, %1, %2;" : "=r"(rem_bar) : "r"(bar_local), "r"(peer));
    }
    const unsigned int src_loc[2] = { smem_u32(&hloc[0][0]), smem_u32(&hloc[1][0]) };

    const float* xwp = g_xw + (size_t)n * 512 * 256 + jbase;

    if (g == 0) {
        // ----- Group A: local-half dotter, never waits on the mbarrier -----
        for (int s = 0; s < 512; s++) {
            const int cur = s & 1;
            if (s > 0) {
                // Wait for B's hloc[cur] writes from step s-1.
                asm volatile("bar.sync 3, 256;" ::: "memory");
            }
            float part = dot128((const ulonglong2*)&hloc[cur][0], W2);
            p_s[cur][j] = part;
            asm volatile("bar.arrive 2, 256;" ::: "memory");
        }
    } else {
        // ----- Group B: remote-half dotter + combiner + sender -----
        const int wchunk = (t - 128) >> 5;          // B warp index 0..3
        const unsigned int coff = wchunk * 128;     // 32 floats per warp chunk
        float xw_cur = xwp[j];
        for (int s = 0; s < 512; s++) {
            const int cur = s & 1;
            const int nxt = cur ^ 1;

            // Prefetch next step's input projection.
            int sn = (s + 1 < 512) ? (s + 1) : s;
            float xw_nxt = xwp[(size_t)sn * 256 + j];

            // A's p_s[cur] is ready well before the peer data arrives: take
            // the barrier + LDS off the post-arrival critical path.
            asm volatile("bar.sync 2, 256;" ::: "memory");
            float psv = p_s[cur][j];

            // Wait for the peer's half of h[cur] (step s-1's send).
            if (s > 0) wait_parity(bar_local, (unsigned)((s & 1) ^ 1));

            float part = dot128((const ulonglong2*)&hrem[cur][0], W2);

            float pre = xw_cur + part + psv;
            float hn  = fast_tanh(pre);
            hloc[nxt][j] = hn;
            xw_cur = xw_nxt;

            if (s < 511) {
                // Release A for step s+1 (non-blocking).
                asm volatile("bar.arrive 3, 256;" ::: "memory");
                // Per-warp chunked send: this warp's 32 floats are written.
                __syncwarp();
                asm volatile("fence.proxy.async.shared::cta;" ::: "memory");
                if ((t & 31) == 0) {
                    if (wchunk == 0) {
                        // Arm our own barrier for the peer's incoming 512B.
                        asm volatile("mbarrier.arrive.expect_tx.shared::cta.b64 _, [%0], %1;"
                                     :: "r"(bar_local), "r"(512) : "memory");
                    }
                    asm volatile(
                        "cp.async.bulk.shared::cluster.shared::cta.mbarrier::complete_tx::bytes "
                        "[%0], [%1], %2, [%3];"
                        :: "r"(rem_dst[nxt] + coff), "r"(src_loc[nxt] + coff),
                           "r"(128), "r"(rem_bar)
                        : "memory");
                }
            }
            out[((size_t)n * 512 + s) * 256 + jbase + j] = hn;
        }
    }

    // Don't exit while the peer may still write into our SMEM.
    asm volatile("barrier.cluster.arrive.aligned;" ::: "memory");
    asm volatile("barrier.cluster.wait.aligned;" ::: "memory");
}

// ---------------------------------------------------------------------------
extern "C" void kernel_launch(void* const* d_in, const int* in_sizes, int n_in,
                              void* d_out, int out_size) {
    const float* x  = (const float*)d_in[0];  // (64,512,256)
    const float* h0 = (const float*)d_in[1];  // (64,256)
    const float* Wx = (const float*)d_in[2];  // (256,256)
    const float* Wh = (const float*)d_in[3];  // (256,256)
    const float* b  = (const float*)d_in[4];  // (256,)
    float* out = (float*)d_out;               // (64,512,256)

    dim3 g1(256, 2);
    gemm_xw<<<g1, 256>>>(x, Wx, b);
    rnn_scan<<<128, 256>>>(h0, Wh, out);
    (void)in_sizes; (void)n_in; (void)out_size;
}